// round 5
// baseline (speedup 1.0000x reference)
#include <cuda_runtime.h>

#define E_ 100
#define V_ 3
#define S_ 100
#define T_ 10
#define NT 128

// Precomputed folded weights (tiny, computed once per launch by mvke_pre)
__device__ float g_w2[V_ * E_];   // w2[v][j] = sum_e of2[v][e] * fc1_w[e][j]
__device__ float g_w3[V_ * E_];   // w3[v][j] = sum_e of3[v][e] * fc4_w[e][j]
__device__ float g_c[V_];         // c[v]  = of2[v] . fc1_b
__device__ float g_c2[V_];        // c2[v] = of3[v] . fc4_b

__global__ void mvke_pre(const float* __restrict__ vk,
                         const float* __restrict__ fc1_w, const float* __restrict__ fc1_b,
                         const float* __restrict__ fc2_w, const float* __restrict__ fc2_b,
                         const float* __restrict__ fc3_w, const float* __restrict__ fc3_b,
                         const float* __restrict__ fc4_w, const float* __restrict__ fc4_b)
{
    __shared__ float of2[V_][E_];
    __shared__ float of3[V_][E_];
    const int tid = threadIdx.x;

    // of2[v] = fc2_w @ vk[v] + fc2_b ;  of3[v] = fc3_w @ vk[v] + fc3_b
    for (int idx = tid; idx < V_ * E_; idx += blockDim.x) {
        int v = idx / E_, e = idx % E_;
        float s2 = fc2_b[e], s3 = fc3_b[e];
        for (int j = 0; j < E_; j++) {
            float vv = vk[v * E_ + j];
            s2 += fc2_w[e * E_ + j] * vv;
            s3 += fc3_w[e * E_ + j] * vv;
        }
        of2[v][e] = s2;
        of3[v][e] = s3;
    }
    __syncthreads();

    // w2[v][j] = sum_e of2[v][e]*fc1_w[e][j] ; w3[v][j] = sum_e of3[v][e]*fc4_w[e][j]
    for (int idx = tid; idx < V_ * E_; idx += blockDim.x) {
        int v = idx / E_, j = idx % E_;
        float s2 = 0.f, s3 = 0.f;
        for (int e = 0; e < E_; e++) {
            s2 += of2[v][e] * fc1_w[e * E_ + j];
            s3 += of3[v][e] * fc4_w[e * E_ + j];
        }
        g_w2[idx] = s2;
        g_w3[idx] = s3;
    }
    if (tid < V_) {
        float s = 0.f, s2 = 0.f;
        for (int e = 0; e < E_; e++) {
            s  += of2[tid][e] * fc1_b[e];
            s2 += of3[tid][e] * fc4_b[e];
        }
        g_c[tid]  = s;
        g_c2[tid] = s2;
    }
}

__device__ __forceinline__ float dot4(float4 a, float4 b) {
    return a.x * b.x + a.y * b.y + a.z * b.z + a.w * b.w;
}

__global__ __launch_bounds__(NT) void mvke_main(
    const float* __restrict__ x, const float* __restrict__ tag,
    const float* __restrict__ fc1_w, const float* __restrict__ fc1_b,
    float* __restrict__ out)
{
    __shared__ float xs[S_][E_];     // 40000 B: x[b] tile
    __shared__ float w2s[V_][E_];
    __shared__ float w3s[V_][E_];
    __shared__ float m1t[V_][S_];    // m1 then sm1, transposed [v][s]
    __shared__ float ys[V_][E_];     // y[v] = sum_s sm1[s,v] x[s]
    __shared__ float ws1s[V_][E_];   // ws1[v] = fc1_w y[v] + fc1_b
    __shared__ float m2s[T_][V_];
    __shared__ float dvs[T_][V_];    // d[t][v] = ws1[v] . tag[t]
    __shared__ float cs[V_], c2s[V_];

    const int b    = blockIdx.x;
    const int tid  = threadIdx.x;
    const int w    = tid >> 5;
    const int lane = tid & 31;
    const float scale = 0.1f;                 // 1/sqrt(DK)
    const float PAD   = -4294967296.0f;       // float32(-(2^32)+1)

    for (int i = tid; i < V_ * E_; i += NT) {
        (&w2s[0][0])[i] = g_w2[i];
        (&w3s[0][0])[i] = g_w3[i];
    }
    if (tid < V_) { cs[tid] = g_c[tid]; c2s[tid] = g_c2[tid]; }
    __syncthreads();

    // ---- Phase A: stream x[b] into smem; m1[s,v] = scale*(x[s].w2[v] + c[v]) with zero-row mask
    const float* xb = x + (size_t)b * (S_ * E_);
    for (int s = w; s < S_; s += (NT / 32)) {
        float d0 = 0.f, d1 = 0.f, d2 = 0.f, sa = 0.f;
        if (lane < 25) {
            float4 xq = reinterpret_cast<const float4*>(xb + s * E_)[lane];
            reinterpret_cast<float4*>(&xs[s][0])[lane] = xq;
            float4 a0 = reinterpret_cast<const float4*>(&w2s[0][0])[lane];
            float4 a1 = reinterpret_cast<const float4*>(&w2s[1][0])[lane];
            float4 a2 = reinterpret_cast<const float4*>(&w2s[2][0])[lane];
            d0 = dot4(xq, a0);
            d1 = dot4(xq, a1);
            d2 = dot4(xq, a2);
            sa = fabsf(xq.x) + fabsf(xq.y) + fabsf(xq.z) + fabsf(xq.w);
        }
        #pragma unroll
        for (int off = 16; off; off >>= 1) {
            d0 += __shfl_down_sync(0xffffffffu, d0, off);
            d1 += __shfl_down_sync(0xffffffffu, d1, off);
            d2 += __shfl_down_sync(0xffffffffu, d2, off);
            sa += __shfl_down_sync(0xffffffffu, sa, off);
        }
        if (lane == 0) {
            bool masked = (sa == 0.0f);
            m1t[0][s] = masked ? PAD : scale * (d0 + cs[0]);
            m1t[1][s] = masked ? PAD : scale * (d1 + cs[1]);
            m1t[2][s] = masked ? PAD : scale * (d2 + cs[2]);
        }
    }
    __syncthreads();

    // ---- Phase B: softmax over S per v (warp v handles column v)
    if (w < V_) {
        const int v = w;
        float vals[4];
        float mx = -3.4e38f;
        #pragma unroll
        for (int i = 0; i < 4; i++) {
            int s = lane + 32 * i;
            vals[i] = (s < S_) ? m1t[v][s] : -3.4e38f;
            mx = fmaxf(mx, vals[i]);
        }
        #pragma unroll
        for (int off = 16; off; off >>= 1)
            mx = fmaxf(mx, __shfl_xor_sync(0xffffffffu, mx, off));
        float sum = 0.f;
        #pragma unroll
        for (int i = 0; i < 4; i++) {
            int s = lane + 32 * i;
            vals[i] = expf(vals[i] - mx);
            if (s < S_) sum += vals[i];
        }
        #pragma unroll
        for (int off = 16; off; off >>= 1)
            sum += __shfl_xor_sync(0xffffffffu, sum, off);
        float inv = 1.0f / sum;
        #pragma unroll
        for (int i = 0; i < 4; i++) {
            int s = lane + 32 * i;
            if (s < S_) m1t[v][s] = vals[i] * inv;
        }
    }
    __syncthreads();

    // ---- Phase C: y[v][e] = sum_s sm1[v][s] * x[s][e]   (thread e, vectorized over s by 4)
    if (tid < E_) {
        float a0 = 0.f, a1 = 0.f, a2 = 0.f;
        for (int s = 0; s < S_; s += 4) {
            float4 p0 = *reinterpret_cast<const float4*>(&m1t[0][s]);
            float4 p1 = *reinterpret_cast<const float4*>(&m1t[1][s]);
            float4 p2 = *reinterpret_cast<const float4*>(&m1t[2][s]);
            float x0 = xs[s][tid], x1 = xs[s + 1][tid];
            float x2 = xs[s + 2][tid], x3 = xs[s + 3][tid];
            a0 += p0.x * x0 + p0.y * x1 + p0.z * x2 + p0.w * x3;
            a1 += p1.x * x0 + p1.y * x1 + p1.z * x2 + p1.w * x3;
            a2 += p2.x * x0 + p2.y * x1 + p2.z * x2 + p2.w * x3;
        }
        ys[0][tid] = a0; ys[1][tid] = a1; ys[2][tid] = a2;
    }
    __syncthreads();

    // ---- Phase D: ws1[v][i] = fc1_w[i,:].y[v] + fc1_b[i]  (warp per row i, coalesced)
    for (int i = w; i < E_; i += (NT / 32)) {
        float d0 = 0.f, d1 = 0.f, d2 = 0.f;
        if (lane < 25) {
            float4 wv = reinterpret_cast<const float4*>(fc1_w + i * E_)[lane];
            float4 y0 = reinterpret_cast<const float4*>(&ys[0][0])[lane];
            float4 y1 = reinterpret_cast<const float4*>(&ys[1][0])[lane];
            float4 y2 = reinterpret_cast<const float4*>(&ys[2][0])[lane];
            d0 = dot4(wv, y0);
            d1 = dot4(wv, y1);
            d2 = dot4(wv, y2);
        }
        #pragma unroll
        for (int off = 16; off; off >>= 1) {
            d0 += __shfl_down_sync(0xffffffffu, d0, off);
            d1 += __shfl_down_sync(0xffffffffu, d1, off);
            d2 += __shfl_down_sync(0xffffffffu, d2, off);
        }
        if (lane == 0) {
            float bb = fc1_b[i];
            ws1s[0][i] = d0 + bb;
            ws1s[1][i] = d1 + bb;
            ws1s[2][i] = d2 + bb;
        }
    }
    __syncthreads();

    // ---- Phase E: m2[t][v] = scale*(tag[t].w3[v] + c2[v]);  d[t][v] = tag[t].ws1[v]
    const float* tb = tag + (size_t)b * (T_ * E_);
    for (int t = w; t < T_; t += (NT / 32)) {
        float m0 = 0.f, m1v = 0.f, m2v = 0.f, e0 = 0.f, e1 = 0.f, e2 = 0.f;
        if (lane < 25) {
            float4 tq = reinterpret_cast<const float4*>(tb + t * E_)[lane];
            float4 b0 = reinterpret_cast<const float4*>(&w3s[0][0])[lane];
            float4 b1 = reinterpret_cast<const float4*>(&w3s[1][0])[lane];
            float4 b2 = reinterpret_cast<const float4*>(&w3s[2][0])[lane];
            float4 u0 = reinterpret_cast<const float4*>(&ws1s[0][0])[lane];
            float4 u1 = reinterpret_cast<const float4*>(&ws1s[1][0])[lane];
            float4 u2 = reinterpret_cast<const float4*>(&ws1s[2][0])[lane];
            m0  = dot4(tq, b0); m1v = dot4(tq, b1); m2v = dot4(tq, b2);
            e0  = dot4(tq, u0); e1  = dot4(tq, u1); e2  = dot4(tq, u2);
        }
        #pragma unroll
        for (int off = 16; off; off >>= 1) {
            m0  += __shfl_down_sync(0xffffffffu, m0,  off);
            m1v += __shfl_down_sync(0xffffffffu, m1v, off);
            m2v += __shfl_down_sync(0xffffffffu, m2v, off);
            e0  += __shfl_down_sync(0xffffffffu, e0,  off);
            e1  += __shfl_down_sync(0xffffffffu, e1,  off);
            e2  += __shfl_down_sync(0xffffffffu, e2,  off);
        }
        if (lane == 0) {
            m2s[t][0] = scale * (m0  + c2s[0]);
            m2s[t][1] = scale * (m1v + c2s[1]);
            m2s[t][2] = scale * (m2v + c2s[2]);
            dvs[t][0] = e0; dvs[t][1] = e1; dvs[t][2] = e2;
        }
    }
    __syncthreads();

    // ---- Phase F: softmax over T per v, then out[b,t] = sum_v sm2[t,v]*d[t,v]
    if (tid < V_) {
        const int v = tid;
        float mx = m2s[0][v];
        #pragma unroll
        for (int t = 1; t < T_; t++) mx = fmaxf(mx, m2s[t][v]);
        float ev[T_];
        float sum = 0.f;
        #pragma unroll
        for (int t = 0; t < T_; t++) { ev[t] = expf(m2s[t][v] - mx); sum += ev[t]; }
        float inv = 1.0f / sum;
        #pragma unroll
        for (int t = 0; t < T_; t++) m2s[t][v] = ev[t] * inv;
    }
    __syncthreads();
    if (tid < T_) {
        const int t = tid;
        out[(size_t)b * T_ + t] =
            m2s[t][0] * dvs[t][0] + m2s[t][1] * dvs[t][1] + m2s[t][2] * dvs[t][2];
    }
}

extern "C" void kernel_launch(void* const* d_in, const int* in_sizes, int n_in,
                              void* d_out, int out_size)
{
    const float* x     = (const float*)d_in[0];
    const float* tag   = (const float*)d_in[1];
    const float* vk    = (const float*)d_in[2];
    const float* fc1_w = (const float*)d_in[3];
    const float* fc1_b = (const float*)d_in[4];
    const float* fc2_w = (const float*)d_in[5];
    const float* fc2_b = (const float*)d_in[6];
    const float* fc3_w = (const float*)d_in[7];
    const float* fc3_b = (const float*)d_in[8];
    const float* fc4_w = (const float*)d_in[9];
    const float* fc4_b = (const float*)d_in[10];
    float* out = (float*)d_out;

    mvke_pre<<<1, 384>>>(vk, fc1_w, fc1_b, fc2_w, fc2_b, fc3_w, fc3_b, fc4_w, fc4_b);
    mvke_main<<<8192, NT>>>(x, tag, fc1_w, fc1_b, out);
}

// round 6
// speedup vs baseline: 1.6018x; 1.6018x over previous
#include <cuda_runtime.h>

#define E_ 100
#define V_ 3
#define S_ 100
#define T_ 10
#define NT 256
#define XP 101   // padded row stride (words); 101 mod 32 = 5, coprime -> conflict-free both axes

// Precomputed folded weights / transposed fc1_w (computed once per launch by mvke_pre)
__device__ float g_w2[V_ * E_];     // w2[v][j] = sum_e of2[v][e] * fc1_w[e][j]
__device__ float g_w3[V_ * E_];     // w3[v][j] = sum_e of3[v][e] * fc4_w[e][j]
__device__ float g_c[V_];           // c[v]  = of2[v] . fc1_b
__device__ float g_c2[V_];          // c2[v] = of3[v] . fc4_b
__device__ float g_fc1T[E_ * E_];   // fc1T[e][i] = fc1_w[i][e]

__global__ void mvke_pre(const float* __restrict__ vk,
                         const float* __restrict__ fc1_w, const float* __restrict__ fc1_b,
                         const float* __restrict__ fc2_w, const float* __restrict__ fc2_b,
                         const float* __restrict__ fc3_w, const float* __restrict__ fc3_b,
                         const float* __restrict__ fc4_w, const float* __restrict__ fc4_b)
{
    __shared__ float of2[V_][E_];
    __shared__ float of3[V_][E_];
    const int tid = threadIdx.x;

    // of2[v] = fc2_w @ vk[v] + fc2_b ;  of3[v] = fc3_w @ vk[v] + fc3_b
    for (int idx = tid; idx < V_ * E_; idx += blockDim.x) {
        int v = idx / E_, e = idx % E_;
        float s2 = fc2_b[e], s3 = fc3_b[e];
        for (int j = 0; j < E_; j++) {
            float vv = vk[v * E_ + j];
            s2 += fc2_w[e * E_ + j] * vv;
            s3 += fc3_w[e * E_ + j] * vv;
        }
        of2[v][e] = s2;
        of3[v][e] = s3;
    }
    __syncthreads();

    // w2[v][j] = sum_e of2[v][e]*fc1_w[e][j] ; w3[v][j] = sum_e of3[v][e]*fc4_w[e][j]
    for (int idx = tid; idx < V_ * E_; idx += blockDim.x) {
        int v = idx / E_, j = idx % E_;
        float s2 = 0.f, s3 = 0.f;
        for (int e = 0; e < E_; e++) {
            s2 += of2[v][e] * fc1_w[e * E_ + j];
            s3 += of3[v][e] * fc4_w[e * E_ + j];
        }
        g_w2[idx] = s2;
        g_w3[idx] = s3;
    }
    // transpose fc1_w (one-time; read by every mvke_main CTA, L2-resident)
    for (int idx = tid; idx < E_ * E_; idx += blockDim.x) {
        int i = idx / E_, e = idx % E_;
        g_fc1T[e * E_ + i] = fc1_w[i * E_ + e];
    }
    if (tid < V_) {
        float s = 0.f, s2 = 0.f;
        for (int e = 0; e < E_; e++) {
            s  += of2[tid][e] * fc1_b[e];
            s2 += of3[tid][e] * fc4_b[e];
        }
        g_c[tid]  = s;
        g_c2[tid] = s2;
    }
}

__global__ __launch_bounds__(NT, 4) void mvke_main(
    const float* __restrict__ x, const float* __restrict__ tag,
    const float* __restrict__ fc1_b,
    float* __restrict__ out)
{
    __shared__ float xs[S_][XP];        // 40400 B: x[b] tile (later rows 0..9 reused for tag)
    __shared__ float w2s[V_ * E_];
    __shared__ float w3s[V_ * E_];
    __shared__ float m1t[V_][S_];       // m1 then sm1, transposed [v][s]
    __shared__ float sas[S_];           // sum|x| per behavior row (mask)
    __shared__ float ys[V_ * E_];       // y[v] = sum_s sm1[s,v] x[s]
    __shared__ float ws1s[V_ * E_];     // ws1[v] = fc1_w y[v] + fc1_b
    __shared__ float m2s[T_][V_];
    __shared__ float dvs[T_][V_];       // d[t][v] = ws1[v] . tag[t]
    __shared__ float cs[V_], c2s[V_];

    const int b    = blockIdx.x;
    const int tid  = threadIdx.x;
    const int w    = tid >> 5;
    const int lane = tid & 31;
    const float scale = 0.1f;               // 1/sqrt(DK)
    const float PAD   = -4294967296.0f;     // float32(-(2^32)+1)

    // stage folded weights
    for (int i = tid; i < V_ * E_; i += NT) {
        w2s[i] = g_w2[i];
        w3s[i] = g_w3[i];
    }
    if (tid < V_) { cs[tid] = g_c[tid]; c2s[tid] = g_c2[tid]; }

    // ---- stage x[b] into padded smem (fully coalesced float4 loads)
    const float* xb = x + (size_t)b * (S_ * E_);
    for (int i4 = tid; i4 < (S_ * E_) / 4; i4 += NT) {
        float4 q = reinterpret_cast<const float4*>(xb)[i4];
        int row = i4 / 25, c = (i4 % 25) * 4;
        xs[row][c]     = q.x;
        xs[row][c + 1] = q.y;
        xs[row][c + 2] = q.z;
        xs[row][c + 3] = q.w;
    }
    __syncthreads();

    // ---- Phase A: m1[v][s] = scale*(x[s].w2[v] + c[v]); thread-per-(s,v), no reductions
    for (int idx = tid; idx < V_ * S_; idx += NT) {
        const int s = idx % S_, v = idx / S_;
        const float* wr = &w2s[v * E_];
        float acc = 0.f, sa = 0.f;
        #pragma unroll 4
        for (int e = 0; e < E_; e++) {
            float xv = xs[s][e];
            acc += xv * wr[e];
            sa  += fabsf(xv);
        }
        m1t[v][s] = scale * (acc + cs[v]);
        if (v == 0) sas[s] = sa;
    }
    __syncthreads();

    // ---- Phase B: softmax over S per v (warp v), mask applied at load
    if (w < V_) {
        const int v = w;
        float vals[4];
        float mx = -3.4e38f;
        #pragma unroll
        for (int i = 0; i < 4; i++) {
            int s = lane + 32 * i;
            vals[i] = (s < S_) ? ((sas[s] == 0.0f) ? PAD : m1t[v][s]) : -3.4e38f;
            mx = fmaxf(mx, vals[i]);
        }
        #pragma unroll
        for (int off = 16; off; off >>= 1)
            mx = fmaxf(mx, __shfl_xor_sync(0xffffffffu, mx, off));
        float sum = 0.f;
        #pragma unroll
        for (int i = 0; i < 4; i++) {
            int s = lane + 32 * i;
            vals[i] = expf(vals[i] - mx);
            if (s < S_) sum += vals[i];
        }
        #pragma unroll
        for (int off = 16; off; off >>= 1)
            sum += __shfl_xor_sync(0xffffffffu, sum, off);
        float inv = 1.0f / sum;
        #pragma unroll
        for (int i = 0; i < 4; i++) {
            int s = lane + 32 * i;
            if (s < S_) m1t[v][s] = vals[i] * inv;
        }
    }
    __syncthreads();

    // ---- Phase C: y[v][e] = sum_s sm1[v][s] * xs[s][e]; thread-per-(v,e)
    for (int idx = tid; idx < V_ * E_; idx += NT) {
        const int e = idx % E_, v = idx / E_;
        const float* pm = &m1t[v][0];
        float acc = 0.f;
        #pragma unroll 4
        for (int s = 0; s < S_; s++)
            acc += pm[s] * xs[s][e];
        ys[idx] = acc;
    }
    __syncthreads();

    // ---- Phase D: ws1[v][i] = fc1T[:,i].y[v] + fc1_b[i]; thread-per-column i, coalesced LDG
    if (tid < E_) {
        const int i = tid;
        float a0 = 0.f, a1 = 0.f, a2 = 0.f;
        #pragma unroll 4
        for (int e = 0; e < E_; e++) {
            float wv = g_fc1T[e * E_ + i];      // lanes i consecutive -> coalesced, L1/L2 hot
            a0 += wv * ys[0 * E_ + e];
            a1 += wv * ys[1 * E_ + e];
            a2 += wv * ys[2 * E_ + e];
        }
        float bb = fc1_b[i];
        ws1s[0 * E_ + i] = a0 + bb;
        ws1s[1 * E_ + i] = a1 + bb;
        ws1s[2 * E_ + i] = a2 + bb;
    }
    // concurrently: stage tag[b] into xs rows 0..9 (xs is dead after Phase C)
    {
        const float* tb = tag + (size_t)b * (T_ * E_);
        for (int i4 = tid; i4 < (T_ * E_) / 4; i4 += NT) {
            float4 q = reinterpret_cast<const float4*>(tb)[i4];
            int row = i4 / 25, c = (i4 % 25) * 4;
            xs[row][c]     = q.x;
            xs[row][c + 1] = q.y;
            xs[row][c + 2] = q.z;
            xs[row][c + 3] = q.w;
        }
    }
    __syncthreads();

    // ---- Phase E: m2[t][v] and d[t][v]; thread-per-(t,v) from smem
    if (tid < T_ * V_) {
        const int t = tid / V_, v = tid % V_;
        const float* w3v = &w3s[v * E_];
        const float* wsv = &ws1s[v * E_];
        float am = 0.f, ad = 0.f;
        #pragma unroll 4
        for (int e = 0; e < E_; e++) {
            float tv = xs[t][e];
            am += tv * w3v[e];
            ad += tv * wsv[e];
        }
        m2s[t][v] = scale * (am + c2s[v]);
        dvs[t][v] = ad;
    }
    __syncthreads();

    // ---- Phase F: softmax over T per v, then out[b,t] = sum_v sm2[t,v]*d[t,v]
    if (tid < V_) {
        const int v = tid;
        float mx = m2s[0][v];
        #pragma unroll
        for (int t = 1; t < T_; t++) mx = fmaxf(mx, m2s[t][v]);
        float ev[T_];
        float sum = 0.f;
        #pragma unroll
        for (int t = 0; t < T_; t++) { ev[t] = expf(m2s[t][v] - mx); sum += ev[t]; }
        float inv = 1.0f / sum;
        #pragma unroll
        for (int t = 0; t < T_; t++) m2s[t][v] = ev[t] * inv;
    }
    __syncthreads();
    if (tid < T_) {
        const int t = tid;
        out[(size_t)b * T_ + t] =
            m2s[t][0] * dvs[t][0] + m2s[t][1] * dvs[t][1] + m2s[t][2] * dvs[t][2];
    }
}

extern "C" void kernel_launch(void* const* d_in, const int* in_sizes, int n_in,
                              void* d_out, int out_size)
{
    const float* x     = (const float*)d_in[0];
    const float* tag   = (const float*)d_in[1];
    const float* vk    = (const float*)d_in[2];
    const float* fc1_w = (const float*)d_in[3];
    const float* fc1_b = (const float*)d_in[4];
    const float* fc2_w = (const float*)d_in[5];
    const float* fc2_b = (const float*)d_in[6];
    const float* fc3_w = (const float*)d_in[7];
    const float* fc3_b = (const float*)d_in[8];
    const float* fc4_w = (const float*)d_in[9];
    const float* fc4_b = (const float*)d_in[10];
    float* out = (float*)d_out;

    mvke_pre<<<1, 384>>>(vk, fc1_w, fc1_b, fc2_w, fc2_b, fc3_w, fc3_b, fc4_w, fc4_b);
    mvke_main<<<8192, NT>>>(x, tag, fc1_b, out);
}

// round 7
// speedup vs baseline: 2.0145x; 1.2576x over previous
#include <cuda_runtime.h>

#define E_ 100
#define V_ 3
#define S_ 100
#define T_ 10
#define NT 256
#define XW 27   // float4 per xs row = 108 floats; 108 mod 32 = 12 -> LDS.128 conflict-free

// Precomputed folded weights / transposed fc1_w (computed once per launch)
__device__ float g_w2[V_ * E_];     // w2[v][j] = sum_e of2[v][e] * fc1_w[e][j]
__device__ float g_w3[V_ * E_];     // w3[v][j] = sum_e of3[v][e] * fc4_w[e][j]
__device__ float g_c[V_];           // c[v]  = of2[v] . fc1_b
__device__ float g_c2[V_];          // c2[v] = of3[v] . fc4_b
__device__ float g_fc1T[E_ * E_];   // fc1T[e][i] = fc1_w[i][e]

__global__ void mvke_pre(const float* __restrict__ vk,
                         const float* __restrict__ fc1_w, const float* __restrict__ fc1_b,
                         const float* __restrict__ fc2_w, const float* __restrict__ fc2_b,
                         const float* __restrict__ fc3_w, const float* __restrict__ fc3_b,
                         const float* __restrict__ fc4_w, const float* __restrict__ fc4_b)
{
    __shared__ float of2[V_][E_];
    __shared__ float of3[V_][E_];
    const int tid = threadIdx.x;

    for (int idx = tid; idx < V_ * E_; idx += blockDim.x) {
        int v = idx / E_, e = idx % E_;
        float s2 = fc2_b[e], s3 = fc3_b[e];
        for (int j = 0; j < E_; j++) {
            float vv = vk[v * E_ + j];
            s2 += fc2_w[e * E_ + j] * vv;
            s3 += fc3_w[e * E_ + j] * vv;
        }
        of2[v][e] = s2;
        of3[v][e] = s3;
    }
    __syncthreads();

    for (int idx = tid; idx < V_ * E_; idx += blockDim.x) {
        int v = idx / E_, j = idx % E_;
        float s2 = 0.f, s3 = 0.f;
        for (int e = 0; e < E_; e++) {
            s2 += of2[v][e] * fc1_w[e * E_ + j];
            s3 += of3[v][e] * fc4_w[e * E_ + j];
        }
        g_w2[idx] = s2;
        g_w3[idx] = s3;
    }
    for (int idx = tid; idx < E_ * E_; idx += blockDim.x) {
        int i = idx / E_, e = idx % E_;
        g_fc1T[e * E_ + i] = fc1_w[i * E_ + e];
    }
    if (tid < V_) {
        float s = 0.f, s2 = 0.f;
        for (int e = 0; e < E_; e++) {
            s  += of2[tid][e] * fc1_b[e];
            s2 += of3[tid][e] * fc4_b[e];
        }
        g_c[tid]  = s;
        g_c2[tid] = s2;
    }
}

__device__ __forceinline__ float dot4(float4 a, float4 b) {
    return a.x * b.x + a.y * b.y + a.z * b.z + a.w * b.w;
}

__global__ __launch_bounds__(NT, 4) void mvke_main(
    const float* __restrict__ x, const float* __restrict__ tag,
    const float* __restrict__ fc1_b,
    float* __restrict__ out)
{
    __shared__ float4 xs4[S_ * XW];      // 43200 B: x[b] (rows 0..9 reused for tag later)
    __shared__ float4 w3s4_[75];         // w3 (read in E)
    __shared__ float4 wA4_[75];          // w2 (A) -> ys (C/D)
    __shared__ float4 wB4_[75];          // m1 half0 / sm1 (B/C) -> ws1 (D/E)
    __shared__ float4 pb4_[75];          // half1 partials for A/C/D
    __shared__ float  sas0[S_];          // sum|x| half0
    __shared__ float  sbuf[S_];          // sum|x| half1 -> m2s[0..29], dvs[30..59]
    __shared__ float  cs[V_], c2s[V_];

    float*  xsf  = (float*)xs4;
    float*  w3s  = (float*)w3s4_;
    float*  wA   = (float*)wA4_;   float4* wA4 = wA4_;
    float*  wB   = (float*)wB4_;   float4* wB4 = wB4_;
    float*  pb   = (float*)pb4_;   float4* pb4 = pb4_;
    float4* w3s4 = w3s4_;
    (void)pb4;

    const int b    = blockIdx.x;
    const int tid  = threadIdx.x;
    const int w    = tid >> 5;
    const int lane = tid & 31;
    const int g    = tid >> 7;       // 0 or 1 (warpgroup half) -- no intra-warp divergence
    const int idx  = tid & 127;      // 0..127; active if < 100
    const float scale = 0.1f;                 // 1/sqrt(DK)
    const float PAD   = -4294967296.0f;       // float32(-(2^32)+1)

    // stage folded weights + x[b]
    for (int i = tid; i < V_ * E_; i += NT) {
        wA[i]  = g_w2[i];
        w3s[i] = g_w3[i];
    }
    if (tid < V_) { cs[tid] = g_c[tid]; c2s[tid] = g_c2[tid]; }
    {
        const float4* xg = reinterpret_cast<const float4*>(x + (size_t)b * (S_ * E_));
        for (int i4 = tid; i4 < (S_ * E_) / 4; i4 += NT) {
            int row = i4 / 25, c = i4 % 25;
            xs4[row * XW + c] = xg[i4];
        }
    }
    __syncthreads();

    // ---- Phase A: raw m1 halves. thread-per-s, 3 v-accums, float4 over e.
    // half g covers e in [0,52) (q 0..12) or [52,100) (q 13..24)
    if (idx < S_) {
        const int s = idx;
        const int q0 = g ? 13 : 0, q1 = g ? 25 : 13;
        const float4* xr = xs4 + s * XW;
        float a0 = 0.f, a1 = 0.f, a2 = 0.f, sa = 0.f;
        #pragma unroll 4
        for (int q = q0; q < q1; q++) {
            float4 xq = xr[q];
            float4 w0 = wA4[q];
            float4 w1 = wA4[25 + q];
            float4 w2q = wA4[50 + q];
            a0 += dot4(xq, w0);
            a1 += dot4(xq, w1);
            a2 += dot4(xq, w2q);
            sa += fabsf(xq.x) + fabsf(xq.y) + fabsf(xq.z) + fabsf(xq.w);
        }
        if (!g) { wB[s] = a0; wB[100 + s] = a1; wB[200 + s] = a2; sas0[s] = sa; }
        else    { pb[s] = a0; pb[100 + s] = a1; pb[200 + s] = a2; sbuf[s] = sa; }
    }
    __syncthreads();

    // ---- Phase B: combine halves + mask + softmax over S per v (warp v)
    if (w < V_) {
        const int v = w;
        float vals[4];
        float mx = -3.4e38f;
        #pragma unroll
        for (int i = 0; i < 4; i++) {
            int s = lane + 32 * i;
            if (s < S_) {
                float raw = wB[v * 100 + s] + pb[v * 100 + s];
                bool msk = (sas0[s] + sbuf[s]) == 0.0f;
                vals[i] = msk ? PAD : scale * (raw + cs[v]);
            } else vals[i] = -3.4e38f;
            mx = fmaxf(mx, vals[i]);
        }
        #pragma unroll
        for (int off = 16; off; off >>= 1)
            mx = fmaxf(mx, __shfl_xor_sync(0xffffffffu, mx, off));
        float sum = 0.f;
        #pragma unroll
        for (int i = 0; i < 4; i++) {
            int s = lane + 32 * i;
            vals[i] = expf(vals[i] - mx);
            if (s < S_) sum += vals[i];
        }
        #pragma unroll
        for (int off = 16; off; off >>= 1)
            sum += __shfl_xor_sync(0xffffffffu, sum, off);
        float inv = 1.0f / sum;
        #pragma unroll
        for (int i = 0; i < 4; i++) {
            int s = lane + 32 * i;
            if (s < S_) wB[v * 100 + s] = vals[i] * inv;   // final sm1
        }
    }
    __syncthreads();

    // ---- Phase C: ys halves. thread-per-e, 3 v-accums, float4 over s.
    if (idx < E_) {
        const int e = idx;
        const int q0 = g ? 13 : 0, q1 = g ? 25 : 13;
        float a0 = 0.f, a1 = 0.f, a2 = 0.f;
        #pragma unroll 4
        for (int q = q0; q < q1; q++) {
            float4 p0 = wB4[q];
            float4 p1 = wB4[25 + q];
            float4 p2 = wB4[50 + q];
            const float* xc = xsf + (4 * q) * (XW * 4) + e;
            float x0 = xc[0];
            float x1 = xc[XW * 4];
            float x2 = xc[2 * XW * 4];
            float x3 = xc[3 * XW * 4];
            a0 += p0.x * x0 + p0.y * x1 + p0.z * x2 + p0.w * x3;
            a1 += p1.x * x0 + p1.y * x1 + p1.z * x2 + p1.w * x3;
            a2 += p2.x * x0 + p2.y * x1 + p2.z * x2 + p2.w * x3;
        }
        if (!g) { wA[e] = a0; wA[100 + e] = a1; wA[200 + e] = a2; }
        else    { pb[e] = a0; pb[100 + e] = a1; pb[200 + e] = a2; }
    }
    __syncthreads();
    for (int i = tid; i < V_ * E_; i += NT) wA[i] += pb[i];   // reduce ys
    __syncthreads();

    // ---- Phase D: ws1 halves. thread-per-i, 3 v-accums, float4 over e, coalesced fc1T LDG.
    if (idx < E_) {
        const int i = idx;
        const int q0 = g ? 13 : 0, q1 = g ? 25 : 13;
        float a0 = 0.f, a1 = 0.f, a2 = 0.f;
        #pragma unroll 4
        for (int q = q0; q < q1; q++) {
            float4 y0 = wA4[q];
            float4 y1 = wA4[25 + q];
            float4 y2 = wA4[50 + q];
            const float* fp = g_fc1T + (4 * q) * E_ + i;
            float f0 = fp[0];
            float f1 = fp[E_];
            float f2 = fp[2 * E_];
            float f3 = fp[3 * E_];
            a0 += f0 * y0.x + f1 * y0.y + f2 * y0.z + f3 * y0.w;
            a1 += f0 * y1.x + f1 * y1.y + f2 * y1.z + f3 * y1.w;
            a2 += f0 * y2.x + f1 * y2.y + f2 * y2.z + f3 * y2.w;
        }
        if (!g) { wB[i] = a0; wB[100 + i] = a1; wB[200 + i] = a2; }
        else    { pb[i] = a0; pb[100 + i] = a1; pb[200 + i] = a2; }
    } else {
        // idle 56 threads stage tag[b] into xs rows 0..9 (x data dead after C)
        const float4* tg = reinterpret_cast<const float4*>(tag + (size_t)b * (T_ * E_));
        int j = g * 28 + (idx - 100);
        for (int i4 = j; i4 < (T_ * E_) / 4; i4 += 56) {
            int row = i4 / 25, c = i4 % 25;
            xs4[row * XW + c] = tg[i4];
        }
    }
    __syncthreads();
    for (int i = tid; i < V_ * E_; i += NT)
        wB[i] = wB[i] + pb[i] + fc1_b[i % E_];               // reduce ws1 + bias
    __syncthreads();

    // ---- Phase E: m2[t][v] and d[t][v]; thread-per-(t,v), float4 over e (smem only)
    if (tid < T_ * V_) {
        const int t = tid / V_, v = tid % V_;
        float am = 0.f, ad = 0.f;
        #pragma unroll 5
        for (int i = 0; i < 25; i++) {
            float4 tq = xs4[t * XW + i];
            float4 wq = w3s4[v * 25 + i];
            float4 uq = wB4[v * 25 + i];
            am += dot4(tq, wq);
            ad += dot4(tq, uq);
        }
        sbuf[tid]      = scale * (am + c2s[v]);  // m2
        sbuf[30 + tid] = ad;                     // d
    }
    __syncthreads();

    // ---- Phase F: softmax over T per v, then out
    if (tid < V_) {
        const int v = tid;
        float mx = sbuf[v];
        #pragma unroll
        for (int t = 1; t < T_; t++) mx = fmaxf(mx, sbuf[t * V_ + v]);
        float ev[T_];
        float sum = 0.f;
        #pragma unroll
        for (int t = 0; t < T_; t++) { ev[t] = expf(sbuf[t * V_ + v] - mx); sum += ev[t]; }
        float inv = 1.0f / sum;
        #pragma unroll
        for (int t = 0; t < T_; t++) sbuf[t * V_ + v] = ev[t] * inv;
    }
    __syncthreads();
    if (tid < T_) {
        const int t = tid;
        out[(size_t)b * T_ + t] =
            sbuf[t * V_ + 0] * sbuf[30 + t * V_ + 0] +
            sbuf[t * V_ + 1] * sbuf[30 + t * V_ + 1] +
            sbuf[t * V_ + 2] * sbuf[30 + t * V_ + 2];
    }
}

extern "C" void kernel_launch(void* const* d_in, const int* in_sizes, int n_in,
                              void* d_out, int out_size)
{
    const float* x     = (const float*)d_in[0];
    const float* tag   = (const float*)d_in[1];
    const float* vk    = (const float*)d_in[2];
    const float* fc1_w = (const float*)d_in[3];
    const float* fc1_b = (const float*)d_in[4];
    const float* fc2_w = (const float*)d_in[5];
    const float* fc2_b = (const float*)d_in[6];
    const float* fc3_w = (const float*)d_in[7];
    const float* fc3_b = (const float*)d_in[8];
    const float* fc4_w = (const float*)d_in[9];
    const float* fc4_b = (const float*)d_in[10];
    float* out = (float*)d_out;

    mvke_pre<<<1, 384>>>(vk, fc1_w, fc1_b, fc2_w, fc2_b, fc3_w, fc3_b, fc4_w, fc4_b);
    mvke_main<<<8192, NT>>>(x, tag, fc1_b, out);
}

// round 8
// speedup vs baseline: 2.2561x; 1.1199x over previous
#include <cuda_runtime.h>
#include <cstdint>

#define E_ 100
#define V_ 3
#define S_ 100
#define T_ 10
#define B_ 8192
#define NT 256

#define XB (S_ * E_ * 4)   // 40000 bytes per batch of x
#define TB (T_ * E_ * 4)   // 4000 bytes per batch of tag

// dynamic smem layout (float offsets); all float4 regions 16B-aligned
#define OX0   0        // x buffer 0: 100x100, unpadded (conflict-free: stride 100 % 32 == 4)
#define OX1   10000    // x buffer 1
#define OTG0  20000    // tag buffer 0: 10x100
#define OTG1  21000    // tag buffer 1
#define OW2   22000    // folded w2 [3][100]
#define OW3   22300    // folded w3 [3][100]
#define OYS   22600    // ys [3][100]
#define OWB   22900    // m1 raw half0 / sm1 / ws1 [3][100]
#define OPB   23200    // half1 partials [3][100]
#define OSAS  23500    // sum|x| half0 [100]
#define OSB   23600    // sum|x| half1 -> m2[0..29], d[30..59]
#define OCS   23700    // c[3] (+pad)
#define OC2S  23704    // c2[3] (+pad)
#define OMBAR 23708    // 2 x u64 mbarriers
#define SMEM_FLOATS 23712
#define SMEM_BYTES  (SMEM_FLOATS * 4)

// Precomputed folded weights / transposed fc1_w (computed once per launch)
__device__ float g_w2[V_ * E_];
__device__ float g_w3[V_ * E_];
__device__ float g_c[V_];
__device__ float g_c2[V_];
__device__ float g_fc1T[E_ * E_];   // fc1T[e][i] = fc1_w[i][e]

__global__ void mvke_pre(const float* __restrict__ vk,
                         const float* __restrict__ fc1_w, const float* __restrict__ fc1_b,
                         const float* __restrict__ fc2_w, const float* __restrict__ fc2_b,
                         const float* __restrict__ fc3_w, const float* __restrict__ fc3_b,
                         const float* __restrict__ fc4_w, const float* __restrict__ fc4_b)
{
    __shared__ float of2[V_][E_];
    __shared__ float of3[V_][E_];
    const int tid = threadIdx.x;

    for (int idx = tid; idx < V_ * E_; idx += blockDim.x) {
        int v = idx / E_, e = idx % E_;
        float s2 = fc2_b[e], s3 = fc3_b[e];
        for (int j = 0; j < E_; j++) {
            float vv = vk[v * E_ + j];
            s2 += fc2_w[e * E_ + j] * vv;
            s3 += fc3_w[e * E_ + j] * vv;
        }
        of2[v][e] = s2;
        of3[v][e] = s3;
    }
    __syncthreads();

    for (int idx = tid; idx < V_ * E_; idx += blockDim.x) {
        int v = idx / E_, j = idx % E_;
        float s2 = 0.f, s3 = 0.f;
        for (int e = 0; e < E_; e++) {
            s2 += of2[v][e] * fc1_w[e * E_ + j];
            s3 += of3[v][e] * fc4_w[e * E_ + j];
        }
        g_w2[idx] = s2;
        g_w3[idx] = s3;
    }
    for (int idx = tid; idx < E_ * E_; idx += blockDim.x) {
        int i = idx / E_, e = idx % E_;
        g_fc1T[e * E_ + i] = fc1_w[i * E_ + e];
    }
    if (tid < V_) {
        float s = 0.f, s2 = 0.f;
        for (int e = 0; e < E_; e++) {
            s  += of2[tid][e] * fc1_b[e];
            s2 += of3[tid][e] * fc4_b[e];
        }
        g_c[tid]  = s;
        g_c2[tid] = s2;
    }
}

__device__ __forceinline__ float dot4(float4 a, float4 b) {
    return a.x * b.x + a.y * b.y + a.z * b.z + a.w * b.w;
}

__device__ __forceinline__ uint32_t smem_u32(const void* p) {
    uint32_t a;
    asm("{ .reg .u64 t; cvta.to.shared.u64 t, %1; cvt.u32.u64 %0, t; }" : "=r"(a) : "l"(p));
    return a;
}

__device__ __forceinline__ void mbar_init(uint32_t m) {
    asm volatile("mbarrier.init.shared.b64 [%0], 1;" :: "r"(m) : "memory");
}
__device__ __forceinline__ void issue_batch(uint32_t m, uint32_t xdst, uint32_t tdst,
                                            const float* xsrc, const float* tsrc) {
    asm volatile("mbarrier.arrive.expect_tx.shared.b64 _, [%0], %1;"
                 :: "r"(m), "r"((uint32_t)(XB + TB)) : "memory");
    asm volatile("cp.async.bulk.shared::cta.global.mbarrier::complete_tx::bytes [%0], [%1], %2, [%3];"
                 :: "r"(xdst), "l"(xsrc), "r"((uint32_t)XB), "r"(m) : "memory");
    asm volatile("cp.async.bulk.shared::cta.global.mbarrier::complete_tx::bytes [%0], [%1], %2, [%3];"
                 :: "r"(tdst), "l"(tsrc), "r"((uint32_t)TB), "r"(m) : "memory");
}
__device__ __forceinline__ void mbar_wait(uint32_t m, int phase) {
    asm volatile(
        "{\n\t"
        ".reg .pred P;\n\t"
        "WL%=:\n\t"
        "mbarrier.try_wait.parity.acquire.cta.shared::cta.b64 P, [%0], %1, 0x989680;\n\t"
        "@!P bra WL%=;\n\t"
        "}"
        :: "r"(m), "r"((uint32_t)phase) : "memory");
}

__global__ __launch_bounds__(NT) void mvke_main(
    const float* __restrict__ x, const float* __restrict__ tag,
    const float* __restrict__ fc1_b,
    float* __restrict__ out)
{
    extern __shared__ float sm[];

    float*  w2s  = sm + OW2;   float4* w2s4 = (float4*)w2s;
    float*  w3s  = sm + OW3;   float4* w3s4 = (float4*)w3s;
    float*  ys   = sm + OYS;   float4* ys4  = (float4*)ys;
    float*  wB   = sm + OWB;   float4* wB4  = (float4*)wB;
    float*  pb   = sm + OPB;
    float*  sas0 = sm + OSAS;
    float*  sbuf = sm + OSB;
    float*  cs   = sm + OCS;
    float*  c2s  = sm + OC2S;

    const int tid  = threadIdx.x;
    const int w    = tid >> 5;
    const int lane = tid & 31;
    const int g    = tid >> 7;       // warpgroup half: 0/1
    const int idx  = tid & 127;
    const float scale = 0.1f;                 // 1/sqrt(DK)
    const float PAD   = -4294967296.0f;       // float32(-(2^32)+1)

    const uint32_t mb0 = smem_u32(sm + OMBAR);
    const uint32_t mb1 = mb0 + 8;
    const uint32_t xd0 = smem_u32(sm + OX0),  xd1 = smem_u32(sm + OX1);
    const uint32_t td0 = smem_u32(sm + OTG0), td1 = smem_u32(sm + OTG1);

    if (tid == 0) { mbar_init(mb0); mbar_init(mb1); }
    // stage folded weights (overlaps nothing critical; once per CTA)
    for (int i = tid; i < V_ * E_; i += NT) {
        w2s[i] = g_w2[i];
        w3s[i] = g_w3[i];
    }
    if (tid < V_) { cs[tid] = g_c[tid]; c2s[tid] = g_c2[tid]; }
    __syncthreads();   // mbar init + weights visible

    const int G = gridDim.x;
    int b = blockIdx.x;
    if (b >= B_) return;

    // prologue: prefetch first batch into buffer 0
    if (tid == 0)
        issue_batch(mb0, xd0, td0, x + (size_t)b * (S_ * E_), tag + (size_t)b * (T_ * E_));

    int ph0 = 0, ph1 = 0;
    int cur = 0;

    for (; b < B_; b += G) {
        const int nb = b + G;
        // prefetch next batch into the other buffer (its last reader finished
        // at the previous iteration's trailing __syncthreads)
        if (nb < B_ && tid == 0) {
            if (cur == 0)
                issue_batch(mb1, xd1, td1, x + (size_t)nb * (S_ * E_), tag + (size_t)nb * (T_ * E_));
            else
                issue_batch(mb0, xd0, td0, x + (size_t)nb * (S_ * E_), tag + (size_t)nb * (T_ * E_));
        }
        // wait for current buffer
        if (cur == 0) { mbar_wait(mb0, ph0); if (tid == 0) {} ph0 ^= 1; }
        else          { mbar_wait(mb1, ph1); ph1 ^= 1; }

        const float*  xsf = sm + (cur ? OX1 : OX0);
        const float4* xs4 = (const float4*)xsf;
        const float4* tg4 = (const float4*)(sm + (cur ? OTG1 : OTG0));

        // ---- Phase A: raw m1 halves. thread-per-s, 3 v-accums, float4 over e.
        if (idx < S_) {
            const int s = idx;
            const int q0 = g ? 13 : 0, q1 = g ? 25 : 13;
            const float4* xr = xs4 + s * 25;
            float a0 = 0.f, a1 = 0.f, a2 = 0.f, sa = 0.f;
            #pragma unroll 4
            for (int q = q0; q < q1; q++) {
                float4 xq = xr[q];
                float4 w0 = w2s4[q];
                float4 w1 = w2s4[25 + q];
                float4 w2q = w2s4[50 + q];
                a0 += dot4(xq, w0);
                a1 += dot4(xq, w1);
                a2 += dot4(xq, w2q);
                sa += fabsf(xq.x) + fabsf(xq.y) + fabsf(xq.z) + fabsf(xq.w);
            }
            if (!g) { wB[s] = a0; wB[100 + s] = a1; wB[200 + s] = a2; sas0[s] = sa; }
            else    { pb[s] = a0; pb[100 + s] = a1; pb[200 + s] = a2; sbuf[s] = sa; }
        }
        __syncthreads();

        // ---- Phase B: combine halves + mask + softmax over S per v (warp v)
        if (w < V_) {
            const int v = w;
            float vals[4];
            float mx = -3.4e38f;
            #pragma unroll
            for (int i = 0; i < 4; i++) {
                int s = lane + 32 * i;
                if (s < S_) {
                    float raw = wB[v * 100 + s] + pb[v * 100 + s];
                    bool msk = (sas0[s] + sbuf[s]) == 0.0f;
                    vals[i] = msk ? PAD : scale * (raw + cs[v]);
                } else vals[i] = -3.4e38f;
                mx = fmaxf(mx, vals[i]);
            }
            #pragma unroll
            for (int off = 16; off; off >>= 1)
                mx = fmaxf(mx, __shfl_xor_sync(0xffffffffu, mx, off));
            float sum = 0.f;
            #pragma unroll
            for (int i = 0; i < 4; i++) {
                int s = lane + 32 * i;
                vals[i] = expf(vals[i] - mx);
                if (s < S_) sum += vals[i];
            }
            #pragma unroll
            for (int off = 16; off; off >>= 1)
                sum += __shfl_xor_sync(0xffffffffu, sum, off);
            float inv = 1.0f / sum;
            #pragma unroll
            for (int i = 0; i < 4; i++) {
                int s = lane + 32 * i;
                if (s < S_) wB[v * 100 + s] = vals[i] * inv;   // final sm1
            }
        }
        __syncthreads();

        // ---- Phase C: ys halves. thread-per-e, 3 v-accums, float4 over s.
        if (idx < E_) {
            const int e = idx;
            const int q0 = g ? 13 : 0, q1 = g ? 25 : 13;
            float a0 = 0.f, a1 = 0.f, a2 = 0.f;
            #pragma unroll 4
            for (int q = q0; q < q1; q++) {
                float4 p0 = wB4[q];
                float4 p1 = wB4[25 + q];
                float4 p2 = wB4[50 + q];
                const float* xc = xsf + (4 * q) * E_ + e;
                float x0 = xc[0];
                float x1 = xc[E_];
                float x2 = xc[2 * E_];
                float x3 = xc[3 * E_];
                a0 += p0.x * x0 + p0.y * x1 + p0.z * x2 + p0.w * x3;
                a1 += p1.x * x0 + p1.y * x1 + p1.z * x2 + p1.w * x3;
                a2 += p2.x * x0 + p2.y * x1 + p2.z * x2 + p2.w * x3;
            }
            if (!g) { ys[e] = a0; ys[100 + e] = a1; ys[200 + e] = a2; }
            else    { pb[e] = a0; pb[100 + e] = a1; pb[200 + e] = a2; }
        }
        __syncthreads();
        for (int i = tid; i < V_ * E_; i += NT) ys[i] += pb[i];
        __syncthreads();

        // ---- Phase D: ws1 halves. thread-per-i, float4 over e, coalesced L1-hot fc1T.
        if (idx < E_) {
            const int i = idx;
            const int q0 = g ? 13 : 0, q1 = g ? 25 : 13;
            float a0 = 0.f, a1 = 0.f, a2 = 0.f;
            #pragma unroll 4
            for (int q = q0; q < q1; q++) {
                float4 y0 = ys4[q];
                float4 y1 = ys4[25 + q];
                float4 y2 = ys4[50 + q];
                const float* fp = g_fc1T + (4 * q) * E_ + i;
                float f0 = fp[0];
                float f1 = fp[E_];
                float f2 = fp[2 * E_];
                float f3 = fp[3 * E_];
                a0 += f0 * y0.x + f1 * y0.y + f2 * y0.z + f3 * y0.w;
                a1 += f0 * y1.x + f1 * y1.y + f2 * y1.z + f3 * y1.w;
                a2 += f0 * y2.x + f1 * y2.y + f2 * y2.z + f3 * y2.w;
            }
            if (!g) { wB[i] = a0; wB[100 + i] = a1; wB[200 + i] = a2; }
            else    { pb[i] = a0; pb[100 + i] = a1; pb[200 + i] = a2; }
        }
        __syncthreads();
        for (int i = tid; i < V_ * E_; i += NT)
            wB[i] = wB[i] + pb[i] + fc1_b[i % E_];            // final ws1
        __syncthreads();

        // ---- Phase E: m2[t][v], d[t][v]; thread-per-(t,v), float4 over e (smem only)
        if (tid < T_ * V_) {
            const int t = tid / V_, v = tid % V_;
            float am = 0.f, ad = 0.f;
            #pragma unroll 5
            for (int i = 0; i < 25; i++) {
                float4 tq = tg4[t * 25 + i];
                float4 wq = w3s4[v * 25 + i];
                float4 uq = wB4[v * 25 + i];
                am += dot4(tq, wq);
                ad += dot4(tq, uq);
            }
            sbuf[tid]      = scale * (am + c2s[v]);  // m2
            sbuf[30 + tid] = ad;                     // d
        }
        __syncthreads();

        // ---- Phase F: softmax over T per v, then out
        if (tid < V_) {
            const int v = tid;
            float mx = sbuf[v];
            #pragma unroll
            for (int t = 1; t < T_; t++) mx = fmaxf(mx, sbuf[t * V_ + v]);
            float ev[T_];
            float sum = 0.f;
            #pragma unroll
            for (int t = 0; t < T_; t++) { ev[t] = expf(sbuf[t * V_ + v] - mx); sum += ev[t]; }
            float inv = 1.0f / sum;
            #pragma unroll
            for (int t = 0; t < T_; t++) sbuf[t * V_ + v] = ev[t] * inv;
        }
        __syncthreads();
        if (tid < T_) {
            const int t = tid;
            out[(size_t)b * T_ + t] =
                sbuf[t * V_ + 0] * sbuf[30 + t * V_ + 0] +
                sbuf[t * V_ + 1] * sbuf[30 + t * V_ + 1] +
                sbuf[t * V_ + 2] * sbuf[30 + t * V_ + 2];
        }
        __syncthreads();   // buffer `cur` free for the prefetch 2 iterations ahead
        cur ^= 1;
    }
}

extern "C" void kernel_launch(void* const* d_in, const int* in_sizes, int n_in,
                              void* d_out, int out_size)
{
    const float* x     = (const float*)d_in[0];
    const float* tag   = (const float*)d_in[1];
    const float* vk    = (const float*)d_in[2];
    const float* fc1_w = (const float*)d_in[3];
    const float* fc1_b = (const float*)d_in[4];
    const float* fc2_w = (const float*)d_in[5];
    const float* fc2_b = (const float*)d_in[6];
    const float* fc3_w = (const float*)d_in[7];
    const float* fc3_b = (const float*)d_in[8];
    const float* fc4_w = (const float*)d_in[9];
    const float* fc4_b = (const float*)d_in[10];
    float* out = (float*)d_out;

    cudaFuncSetAttribute(mvke_main, cudaFuncAttributeMaxDynamicSharedMemorySize, SMEM_BYTES);

    int sms = 148;
    cudaDeviceGetAttribute(&sms, cudaDevAttrMultiProcessorCount, 0);
    int grid = 2 * sms;
    if (grid > B_) grid = B_;

    mvke_pre<<<1, 384>>>(vk, fc1_w, fc1_b, fc2_w, fc2_b, fc3_w, fc3_b, fc4_w, fc4_b);
    mvke_main<<<grid, NT, SMEM_BYTES>>>(x, tag, fc1_b, out);
}